// round 7
// baseline (speedup 1.0000x reference)
#include <cuda_runtime.h>
#include <cstdint>

// Sparsemax over rows of 16384 x 4096 fp32.
// Persistent CTAs; next row prefetched via cp.async into a shared double
// buffer. Exact sort-free tau: candidates {x > rowmax-1} + Michelot fixed
// point. The FIRST Michelot iteration is fused into the gather pass
// (block-wide sum S and count C of candidates -> t1 = (S-1)/C), so the
// post-barrier solver only runs 1-2 tiny residual iterations, redundantly
// per warp (no broadcast barrier). Full-row fallback on candidate overflow
// (S, C stay exact there, so t1 remains a valid Michelot iterate).

#define N_COLS      4096
#define THREADS     256
#define CAND_CAP    1024
#define CTAS_PER_SM 6
#define NBLOCKS     (152 * CTAS_PER_SM)   // one persistent wave on GB300

__device__ __forceinline__ unsigned enc_f(float f) {
    unsigned u = __float_as_uint(f);
    return (u & 0x80000000u) ? ~u : (u | 0x80000000u);   // order-preserving
}
__device__ __forceinline__ float dec_f(unsigned e) {
    unsigned u = (e & 0x80000000u) ? (e & 0x7fffffffu) : ~e;
    return __uint_as_float(u);
}

__global__ __launch_bounds__(THREADS, CTAS_PER_SM)
void sparsemax_kernel(const float* __restrict__ x, float* __restrict__ out,
                      int rows) {
    __shared__ float    buf[2][N_COLS];     // 32 KB double buffer
    __shared__ float    cand[CAND_CAP];     // 4 KB
    __shared__ unsigned sh_maxbits[2];      // parity-buffered
    __shared__ int      sh_cnt[2];
    __shared__ float    sh_sum[2];

    const int tid    = threadIdx.x;
    const int lane   = tid & 31;
    const int stride = gridDim.x;

    // ---- prologue: init both counter slots, prefetch first row ----
    if (tid == 0) {
        sh_maxbits[0] = 0u; sh_maxbits[1] = 0u;
        sh_cnt[0] = 0;      sh_cnt[1] = 0;
        sh_sum[0] = 0.0f;   sh_sum[1] = 0.0f;
    }
    int r0 = blockIdx.x;
    if (r0 < rows) {
        const float4* g = reinterpret_cast<const float4*>(x + (size_t)r0 * N_COLS);
        uint32_t s = (uint32_t)__cvta_generic_to_shared(&buf[0][0]);
#pragma unroll
        for (int k = 0; k < 4; k++) {
            uint32_t saddr = s + (uint32_t)(tid + k * THREADS) * 16u;
            asm volatile("cp.async.cg.shared.global [%0], [%1], 16;\n"
                         :: "r"(saddr), "l"(g + tid + k * THREADS));
        }
    }
    asm volatile("cp.async.commit_group;\n" ::: "memory");

    int p = 0;
    for (int r = r0; r < rows; r += stride, p ^= 1) {
        // ---- prefetch next row into buf[p^1] (overlaps this row's tau) ----
        const int rn = r + stride;
        if (rn < rows) {
            const float4* g = reinterpret_cast<const float4*>(x + (size_t)rn * N_COLS);
            uint32_t s = (uint32_t)__cvta_generic_to_shared(&buf[p ^ 1][0]);
#pragma unroll
            for (int k = 0; k < 4; k++) {
                uint32_t saddr = s + (uint32_t)(tid + k * THREADS) * 16u;
                asm volatile("cp.async.cg.shared.global [%0], [%1], 16;\n"
                             :: "r"(saddr), "l"(g + tid + k * THREADS));
            }
        }
        asm volatile("cp.async.commit_group;\n" ::: "memory");

        // wait for buf[p] (older group), leave the prefetch in flight
        asm volatile("cp.async.wait_group 1;\n" ::: "memory");
        __syncthreads();                                     // B1

        // reset the OTHER parity's slots: their last readers passed B1,
        // their next users are ordered by the next iteration's B1.
        if (tid == 0) {
            sh_maxbits[p ^ 1] = 0u;
            sh_cnt[p ^ 1] = 0;
            sh_sum[p ^ 1] = 0.0f;
        }

        const float4* b = reinterpret_cast<const float4*>(&buf[p][0]);

        // ---- pass 1: row max (REDUX warp max + one shared atomicMax) ----
        float4 v[4];
        float m = -3.402823466e38f;
#pragma unroll
        for (int k = 0; k < 4; k++) {
            v[k] = b[tid + k * THREADS];
            m = fmaxf(m, fmaxf(fmaxf(v[k].x, v[k].y), fmaxf(v[k].z, v[k].w)));
        }
        unsigned we = __reduce_max_sync(0xffffffffu, enc_f(m));
        if (lane == 0) atomicMax(&sh_maxbits[p], we);
        __syncthreads();                                     // B2

        const float thresh = dec_f(sh_maxbits[p]) - 1.0f;   // tau* >= thresh

        // ---- pass 2: gather candidates + fused Michelot iteration 1 ----
        float s_part = 0.0f;
#pragma unroll
        for (int k = 0; k < 4; k++) {
            float vals[4] = {v[k].x, v[k].y, v[k].z, v[k].w};
#pragma unroll
            for (int j = 0; j < 4; j++) {
                if (vals[j] > thresh) {
                    s_part += vals[j];
                    int q = atomicAdd(&sh_cnt[p], 1);
                    if (q < CAND_CAP) cand[q] = vals[j];
                }
            }
        }
#pragma unroll
        for (int o = 16; o > 0; o >>= 1)
            s_part += __shfl_xor_sync(0xffffffffu, s_part, o);
        if (lane == 0) atomicAdd(&sh_sum[p], s_part);
        __syncthreads();                                     // B3

        // ---- residual Michelot (redundant per warp; usually 1-2 iters) ----
        float tau;
        {
            const int   C = sh_cnt[p];                 // exact even on overflow
            const float S = sh_sum[p];                 // exact even on overflow
            const float* src = cand;
            int nn = C;
            if (C > CAND_CAP) { nn = N_COLS; src = &buf[p][0]; }  // rare, exact
            float t = (S - 1.0f) / (float)C;           // Michelot iterate 1
            int c_prev = C;
            for (;;) {
                float s = 0.0f;
                int   c = 0;
                for (int i = lane; i < nn; i += 32) {
                    float z = src[i];
                    if (z > t) { s += z; c++; }
                }
#pragma unroll
                for (int o = 16; o > 0; o >>= 1)
                    s += __shfl_xor_sync(0xffffffffu, s, o);
                c = __reduce_add_sync(0xffffffffu, c);
                if (c == c_prev) break;        // support stabilized -> exact tau
                t = (s - 1.0f) / (float)c;     // c >= 1 (rowmax in support)
                c_prev = c;
            }
            tau = t;
        }

        // ---- pass 3: write max(x - tau, 0), streaming stores ----
        float4* orow = reinterpret_cast<float4*>(out + (size_t)r * N_COLS);
#pragma unroll
        for (int k = 0; k < 4; k++) {
            float4 w = b[tid + k * THREADS];
            float4 o;
            o.x = fmaxf(w.x - tau, 0.0f);
            o.y = fmaxf(w.y - tau, 0.0f);
            o.z = fmaxf(w.z - tau, 0.0f);
            o.w = fmaxf(w.w - tau, 0.0f);
            __stcs(&orow[tid + k * THREADS], o);
        }
    }
}

extern "C" void kernel_launch(void* const* d_in, const int* in_sizes, int n_in,
                              void* d_out, int out_size) {
    const float* x = (const float*)d_in[0];
    float* out = (float*)d_out;
    const int rows = in_sizes[0] / N_COLS;   // 16384
    sparsemax_kernel<<<NBLOCKS, THREADS>>>(x, out, rows);
}